// round 6
// baseline (speedup 1.0000x reference)
#include <cuda_runtime.h>
#include <cuda_bf16.h>
#include <cstdint>

#define BATCH 128
#define NWALK 64
#define LWALK 32
#define TD 108
#define PD 19
#define FDIM 128
#define MDIM 128

// walk embeddings after Wl: [s][walk][128]
__device__ float g_emb[2 * BATCH * NWALK * MDIM];
// W fragments in exact mma-B layout. [q/k][ks][n8][lane] hi-only; V has hi+lo.
__device__ __align__(16) uint2 g_wqk[2][8][16][32];
__device__ __align__(16) uint4 g_wv[8][16][32];

// ---------------- helpers ----------------------------------------------------
__device__ __forceinline__ uint32_t smem_to_u32(const void* p) {
    uint32_t a;
    asm("{ .reg .u64 t; cvta.to.shared.u64 t, %1; cvt.u32.u64 %0, t; }" : "=r"(a) : "l"(p));
    return a;
}
__device__ __forceinline__ void ldsm4(uint32_t r[4], uint32_t addr) {
    asm volatile("ldmatrix.sync.aligned.m8n8.x4.shared.b16 {%0,%1,%2,%3}, [%4];"
                 : "=r"(r[0]), "=r"(r[1]), "=r"(r[2]), "=r"(r[3]) : "r"(addr));
}
__device__ __forceinline__ void mma16816(float d[4], const uint32_t a[4], const uint32_t b[2]) {
    asm volatile("mma.sync.aligned.m16n8k16.row.col.f32.bf16.bf16.f32 "
                 "{%0,%1,%2,%3},{%4,%5,%6,%7},{%8,%9},{%0,%1,%2,%3};"
                 : "+f"(d[0]), "+f"(d[1]), "+f"(d[2]), "+f"(d[3])
                 : "r"(a[0]), "r"(a[1]), "r"(a[2]), "r"(a[3]), "r"(b[0]), "r"(b[1]));
}
__device__ __forceinline__ uint32_t pack_bf2(float a, float b) {
    __nv_bfloat162 h = __floats2bfloat162_rn(a, b);
    uint32_t r; memcpy(&r, &h, 4); return r;
}

// SMEM layout (bytes); tile rows are 272B (136 bf16)
#define XHI   0
#define KT    34816      // x_lo during QKV; k-tile (bf16) after
#define VS    69632      // fp32 [128][132]
#define BQS   137216
#define BKS   137728
#define BVS   138240
#define CPOFF 138752     // coefpart [8][32] f32
#define CSOFF 139776     // coef [4][32] f32
#define OUTS  140288     // out_s [4][128] f32
#define SMEM_W_TOTAL 142336
#define ROWB 272

// ---------------------------------------------------------------------------
// prep: W[f][j] fp32 -> mma B-fragment layout.
// fragment (ks, n8, lane): n = n8*8 + (l>>2), k0 = ks*16 + 2*(l&3)
//   b0 = {W[k0][n], W[k0+1][n]}   b1 = {W[k0+8][n], W[k0+9][n]}
// ---------------------------------------------------------------------------
__global__ void prep_w_kernel(const float* __restrict__ Wq,
                              const float* __restrict__ Wk,
                              const float* __restrict__ Wv)
{
    const int idx = blockIdx.x * 256 + threadIdx.x;   // 0..12287
    const int l   = idx & 31;
    const int n8  = (idx >> 5) & 15;
    const int ks  = (idx >> 9) & 7;
    const int sel = idx >> 12;                        // 0=q 1=k 2=v
    const int n   = n8 * 8 + (l >> 2);
    const int k0  = ks * 16 + 2 * (l & 3);
    if (sel < 2) {
        const float* W = sel ? Wk : Wq;
        uint2 r;
        r.x = pack_bf2(W[k0 * FDIM + n], W[(k0 + 1) * FDIM + n]);
        r.y = pack_bf2(W[(k0 + 8) * FDIM + n], W[(k0 + 9) * FDIM + n]);
        g_wqk[sel][ks][n8][l] = r;
    } else {
        const float w00 = Wv[k0 * FDIM + n],       w01 = Wv[(k0 + 1) * FDIM + n];
        const float w10 = Wv[(k0 + 8) * FDIM + n], w11 = Wv[(k0 + 9) * FDIM + n];
        const float h00 = __bfloat162float(__float2bfloat16(w00));
        const float h01 = __bfloat162float(__float2bfloat16(w01));
        const float h10 = __bfloat162float(__float2bfloat16(w10));
        const float h11 = __bfloat162float(__float2bfloat16(w11));
        uint4 r;
        r.x = pack_bf2(h00, h01);
        r.y = pack_bf2(h10, h11);
        r.z = pack_bf2(w00 - h00, w01 - h01);
        r.w = pack_bf2(w10 - h10, w11 - h11);
        g_wv[ks][n8][l] = r;
    }
}

// ---------------------------------------------------------------------------
// Walk kernel: 1 CTA = 4 walks of one sign. grid = 4096, 256 threads.
// ---------------------------------------------------------------------------
__global__ __launch_bounds__(256, 1)
void walk_attn_mma_kernel(
    const float* __restrict__ timef,
    const float* __restrict__ ppf,
    const float* __restrict__ pnf,
    const float* __restrict__ weightp,
    const int*   __restrict__ signp,
    const float* __restrict__ bq, const float* __restrict__ bk,
    const float* __restrict__ bv,
    const float* __restrict__ Wl, const float* __restrict__ bl)
{
    extern __shared__ char smem[];
    const uint32_t sb = smem_to_u32(smem);
    const int tid = threadIdx.x;
    const int w   = tid >> 5;
    const int l   = tid & 31;
    const int m0  = w * 16;
    const int walk_l = w >> 1;
    const int bx  = blockIdx.x;
    const int s   = bx >> 11;
    const int g   = bx & 2047;

    float* bq_s = (float*)(smem + BQS);
    float* bk_s = (float*)(smem + BKS);
    float* bv_s = (float*)(smem + BVS);
    float* cp_s = (float*)(smem + CPOFF);
    float* coef_s = (float*)(smem + CSOFF);
    float* out_s  = (float*)(smem + OUTS);
    float* v_s    = (float*)(smem + VS);

    if (tid < 128) { bq_s[tid] = bq[tid]; bk_s[tid] = bk[tid]; bv_s[tid] = bv[tid]; }

    // ---- build X hi/lo tiles ----
    #pragma unroll 4
    for (int it = 0; it < 32; it++) {
        const int id = tid + 256 * it;
        const int r  = id >> 6;
        const int f0 = (id & 63) * 2;
        const int wg = g * 4 + (r >> 5);
        const int e  = wg * LWALK + (r & 31);
        float x0, x1;
        {
            const int f = f0;
            if (f < PD) {
                const bool usep = (signp[e] > 0) != (s == 1);
                x0 = usep ? ppf[e * PD + f] : pnf[e * PD + f];
            } else x0 = timef[e * TD + (f - PD)];
        }
        {
            const int f = f0 + 1;
            if (f < PD) {
                const bool usep = (signp[e] > 0) != (s == 1);
                x1 = usep ? ppf[e * PD + f] : pnf[e * PD + f];
            } else if (f < FDIM - 1) x1 = timef[e * TD + (f - PD)];
            else x1 = weightp[e];
        }
        const float h0 = __bfloat162float(__float2bfloat16(x0));
        const float h1 = __bfloat162float(__float2bfloat16(x1));
        const uint32_t o = (uint32_t)r * ROWB + (uint32_t)f0 * 2;
        *(uint32_t*)(smem + XHI + o) = pack_bf2(h0, h1);
        *(uint32_t*)(smem + KT  + o) = pack_bf2(x0 - h0, x1 - h1);   // x_lo
    }
    __syncthreads();

    // A-side ldmatrix addresses
    const uint32_t aRow = (uint32_t)(m0 + (l & 15));
    const uint32_t aCol = (uint32_t)((l >> 4) << 4);
    const uint32_t aHiB = sb + XHI + aRow * ROWB + aCol;
    // B-side (scores) ldmatrix address components
    const uint32_t bRow = (uint32_t)((l & 7) + ((l >> 4) << 3));
    const uint32_t bCol = (uint32_t)(((l >> 3) & 1) << 4);

    const int r1 = m0 + (l >> 2);
    const int c0 = (l & 3) * 2;

    // ================= V GEMM: 3-term split =================
    {
        float vacc[16][4];
        #pragma unroll
        for (int n = 0; n < 16; n++)
            #pragma unroll
            for (int i = 0; i < 4; i++) vacc[n][i] = 0.f;
        #pragma unroll
        for (int ks = 0; ks < 8; ks++) {
            uint32_t ah[4], al[4];
            ldsm4(ah, aHiB + ks * 32);
            ldsm4(al, aHiB + (KT - XHI) + ks * 32);
            #pragma unroll
            for (int half = 0; half < 2; half++) {
                uint4 bf[8];
                #pragma unroll
                for (int i = 0; i < 8; i++) bf[i] = g_wv[ks][half * 8 + i][l];
                #pragma unroll
                for (int i = 0; i < 8; i++) {
                    const int nt = half * 8 + i;
                    mma16816(vacc[nt], ah, &bf[i].x);
                    mma16816(vacc[nt], ah, &bf[i].z);
                    mma16816(vacc[nt], al, &bf[i].x);
                }
            }
        }
        #pragma unroll
        for (int nt = 0; nt < 16; nt++) {
            const int cc = nt * 8 + c0;
            v_s[r1 * 132 + cc]         = vacc[nt][0];
            v_s[r1 * 132 + cc + 1]     = vacc[nt][1];
            v_s[(r1 + 8) * 132 + cc]   = vacc[nt][2];
            v_s[(r1 + 8) * 132 + cc+1] = vacc[nt][3];
        }
    }

    // ================= Q GEMM: single term =================
    uint32_t qph[16][2];
    {
        float acc[16][4];
        #pragma unroll
        for (int n = 0; n < 16; n++)
            #pragma unroll
            for (int i = 0; i < 4; i++) acc[n][i] = 0.f;
        #pragma unroll
        for (int ks = 0; ks < 8; ks++) {
            uint32_t ah[4];
            ldsm4(ah, aHiB + ks * 32);
            uint2 bf[16];
            #pragma unroll
            for (int n8 = 0; n8 < 16; n8++) bf[n8] = g_wqk[0][ks][n8][l];
            #pragma unroll
            for (int n8 = 0; n8 < 16; n8++) mma16816(acc[n8], ah, &bf[n8].x);
        }
        #pragma unroll
        for (int nt = 0; nt < 16; nt++) {
            const int cc = nt * 8 + c0;
            qph[nt][0] = pack_bf2(acc[nt][0] + bq_s[cc], acc[nt][1] + bq_s[cc + 1]);
            qph[nt][1] = pack_bf2(acc[nt][2] + bq_s[cc], acc[nt][3] + bq_s[cc + 1]);
        }
    }
    __syncthreads();   // all warps done reading x_lo -> KT region reusable

    // ================= K GEMM: single term, write k bf16 over x_lo ==========
    {
        float acc[16][4];
        #pragma unroll
        for (int n = 0; n < 16; n++)
            #pragma unroll
            for (int i = 0; i < 4; i++) acc[n][i] = 0.f;
        #pragma unroll
        for (int ks = 0; ks < 8; ks++) {
            uint32_t ah[4];
            ldsm4(ah, aHiB + ks * 32);
            uint2 bf[16];
            #pragma unroll
            for (int n8 = 0; n8 < 16; n8++) bf[n8] = g_wqk[1][ks][n8][l];
            #pragma unroll
            for (int n8 = 0; n8 < 16; n8++) mma16816(acc[n8], ah, &bf[n8].x);
        }
        #pragma unroll
        for (int nt = 0; nt < 16; nt++) {
            const int cc = nt * 8 + c0;
            const uint32_t o1 = (uint32_t)r1 * ROWB + (uint32_t)cc * 2;
            const uint32_t o2 = (uint32_t)(r1 + 8) * ROWB + (uint32_t)cc * 2;
            *(uint32_t*)(smem + KT + o1) =
                pack_bf2(acc[nt][0] + bk_s[cc], acc[nt][1] + bk_s[cc + 1]);
            *(uint32_t*)(smem + KT + o2) =
                pack_bf2(acc[nt][2] + bk_s[cc], acc[nt][3] + bk_s[cc + 1]);
        }
    }
    __syncthreads();   // k tiles visible

    // ================= scores: single term =================
    float sacc[4][4];
    #pragma unroll
    for (int n = 0; n < 4; n++)
        #pragma unroll
        for (int i = 0; i < 4; i++) sacc[n][i] = 0.f;
    {
        const uint32_t kRow = (uint32_t)(walk_l * 32) + bRow;
        #pragma unroll
        for (int ks = 0; ks < 8; ks++) {
            const uint32_t ah[4] = {qph[2*ks][0], qph[2*ks][1], qph[2*ks+1][0], qph[2*ks+1][1]};
            #pragma unroll
            for (int np = 0; np < 2; np++) {
                uint32_t bh[4];
                ldsm4(bh, sb + KT + (kRow + np * 16) * ROWB + bCol + ks * 32);
                mma16816(sacc[2*np],   ah, bh);
                mma16816(sacc[2*np+1], ah, bh + 2);
            }
        }
    }

    // ---- softmax rows + 16-row column sums ----
    {
        const float scale = 0.08838834764831845f;
        float t[4][2];
        #pragma unroll
        for (int h = 0; h < 2; h++) {
            float x[4][2], mx = -1e30f;
            #pragma unroll
            for (int nt = 0; nt < 4; nt++) {
                x[nt][0] = sacc[nt][2*h]     * scale;
                x[nt][1] = sacc[nt][2*h + 1] * scale;
                mx = fmaxf(mx, fmaxf(x[nt][0], x[nt][1]));
            }
            mx = fmaxf(mx, __shfl_xor_sync(0xffffffffu, mx, 1));
            mx = fmaxf(mx, __shfl_xor_sync(0xffffffffu, mx, 2));
            float sum = 0.f;
            #pragma unroll
            for (int nt = 0; nt < 4; nt++) {
                x[nt][0] = __expf(x[nt][0] - mx);
                x[nt][1] = __expf(x[nt][1] - mx);
                sum += x[nt][0] + x[nt][1];
            }
            sum += __shfl_xor_sync(0xffffffffu, sum, 1);
            sum += __shfl_xor_sync(0xffffffffu, sum, 2);
            const float inv = 1.f / sum;
            #pragma unroll
            for (int nt = 0; nt < 4; nt++) {
                const float p0 = x[nt][0] * inv;
                const float p1 = x[nt][1] * inv;
                if (h == 0) { t[nt][0] = p0;  t[nt][1] = p1; }
                else        { t[nt][0] += p0; t[nt][1] += p1; }
            }
        }
        #pragma unroll
        for (int o = 4; o <= 16; o <<= 1)
            #pragma unroll
            for (int nt = 0; nt < 4; nt++) {
                t[nt][0] += __shfl_xor_sync(0xffffffffu, t[nt][0], o);
                t[nt][1] += __shfl_xor_sync(0xffffffffu, t[nt][1], o);
            }
        if (l < 4) {
            #pragma unroll
            for (int nt = 0; nt < 4; nt++) {
                cp_s[w * 32 + nt * 8 + l * 2]     = t[nt][0];
                cp_s[w * 32 + nt * 8 + l * 2 + 1] = t[nt][1];
            }
        }
    }
    __syncthreads();

    if (tid < 128) {
        const int wk = tid >> 5, m = tid & 31;
        coef_s[tid] = cp_s[(2 * wk) * 32 + m] + cp_s[(2 * wk + 1) * 32 + m];
    }
    __syncthreads();

    // ---- out = coef . V + 32*bv ----
    #pragma unroll
    for (int rep = 0; rep < 2; rep++) {
        const int idx = tid + rep * 256;
        const int wk = idx >> 7;
        const int j  = idx & 127;
        float o = 32.f * bv_s[j];
        #pragma unroll 8
        for (int m = 0; m < 32; m++)
            o += coef_s[wk * 32 + m] * v_s[(wk * 32 + m) * 132 + j];
        out_s[idx] = o;
    }
    __syncthreads();

    // ---- fused Wl + bl (fp32 exact) ----
    #pragma unroll
    for (int rep = 0; rep < 2; rep++) {
        const int idx = tid + rep * 256;
        const int wk = idx >> 7;
        const int m  = idx & 127;
        float acc = bl[m];
        #pragma unroll 8
        for (int f = 0; f < 128; f++)
            acc += out_s[wk * 128 + f] * Wl[f * 128 + m];
        const int wg = g * 4 + wk;
        g_emb[((size_t)(s * 8192 + wg)) * MDIM + m] = acc;
    }
}

// ---------------------------------------------------------------------------
// Path kernel (fp32): per-(b, sign) attention over L=64, D=128.
// ---------------------------------------------------------------------------
__global__ void path_attn_kernel(
    const float* __restrict__ Wqp, const float* __restrict__ bqp,
    const float* __restrict__ Wkp, const float* __restrict__ bkp,
    const float* __restrict__ Wvp, const float* __restrict__ bvp,
    float* __restrict__ out)
{
    extern __shared__ float sm[];
    float* xT       = sm;
    float* q        = xT + 8192;
    float* kk       = q + 8192;
    float* v        = kk + 8320;
    float* coefpart = v + 8192;
    float* coef     = coefpart + 1024;

    const int bx  = blockIdx.x;
    const int s   = bx >> 7;
    const int b   = bx & 127;
    const int tid = threadIdx.x;

    const float* x = g_emb + ((size_t)(s * BATCH + b) * NWALK) * MDIM;
    for (int id = tid; id < 64 * 128; id += 512) {
        const int l = id & 63;
        const int d = id >> 6;
        xT[d * 64 + l] = x[l * 128 + d];
    }
    __syncthreads();
    {
        const int j  = tid & 127;
        const int rg = tid >> 7;
        float accq[16], acck[16], accv[16];
        const float bqj = bqp[j], bkj = bkp[j], bvj = bvp[j];
        #pragma unroll
        for (int i = 0; i < 16; i++) { accq[i] = bqj; acck[i] = bkj; accv[i] = bvj; }
        const float4* xT4 = (const float4*)xT;
        #pragma unroll 2
        for (int f = 0; f < FDIM; f++) {
            const float wq = Wqp[f * FDIM + j];
            const float wk = Wkp[f * FDIM + j];
            const float wv = Wvp[f * FDIM + j];
            #pragma unroll
            for (int k4 = 0; k4 < 4; k4++) {
                const float4 xv = xT4[f * 16 + rg * 4 + k4];
                accq[k4*4+0] += xv.x * wq; accq[k4*4+1] += xv.y * wq;
                accq[k4*4+2] += xv.z * wq; accq[k4*4+3] += xv.w * wq;
                acck[k4*4+0] += xv.x * wk; acck[k4*4+1] += xv.y * wk;
                acck[k4*4+2] += xv.z * wk; acck[k4*4+3] += xv.w * wk;
                accv[k4*4+0] += xv.x * wv; accv[k4*4+1] += xv.y * wv;
                accv[k4*4+2] += xv.z * wv; accv[k4*4+3] += xv.w * wv;
            }
        }
        #pragma unroll
        for (int i = 0; i < 16; i++) {
            const int r = rg * 16 + i;
            q[r * 128 + j] = accq[i];
            kk[r * 130 + j] = acck[i];
            v[r * 128 + j] = accv[i];
        }
    }
    __syncthreads();
    {
        const int m = tid & 31;
        const int w = tid >> 5;
        float sc0[4] = {0.f,0.f,0.f,0.f};
        float sc1[4] = {0.f,0.f,0.f,0.f};
        for (int f = 0; f < FDIM; f++) {
            const float kf0 = kk[m * 130 + f];
            const float kf1 = kk[(m + 32) * 130 + f];
            #pragma unroll
            for (int i = 0; i < 4; i++) {
                const float qf = q[(4 * w + i) * 128 + f];
                sc0[i] += qf * kf0;
                sc1[i] += qf * kf1;
            }
        }
        const float scale = 0.08838834764831845f;
        float cp0 = 0.f, cp1 = 0.f;
        #pragma unroll
        for (int i = 0; i < 4; i++) {
            float x0 = sc0[i] * scale;
            float x1 = sc1[i] * scale;
            float mx = fmaxf(x0, x1);
            #pragma unroll
            for (int o = 16; o > 0; o >>= 1)
                mx = fmaxf(mx, __shfl_xor_sync(0xffffffffu, mx, o));
            const float e0 = __expf(x0 - mx);
            const float e1 = __expf(x1 - mx);
            float sme = e0 + e1;
            #pragma unroll
            for (int o = 16; o > 0; o >>= 1)
                sme += __shfl_xor_sync(0xffffffffu, sme, o);
            const float inv = 1.f / sme;
            cp0 += e0 * inv;
            cp1 += e1 * inv;
        }
        coefpart[w * 64 + m]      = cp0;
        coefpart[w * 64 + m + 32] = cp1;
    }
    __syncthreads();
    if (tid < 64) {
        float c = 0.f;
        #pragma unroll
        for (int w = 0; w < 16; w++) c += coefpart[w * 64 + tid];
        coef[tid] = c;
    }
    __syncthreads();
    if (tid < 128) {
        float o = 0.f;
        #pragma unroll 8
        for (int m = 0; m < 64; m++) o += coef[m] * v[m * 128 + tid];
        out[(size_t)(s * BATCH + b) * MDIM + tid] = o;
    }
}

// ---------------------------------------------------------------------------
extern "C" void kernel_launch(void* const* d_in, const int* in_sizes, int n_in,
                              void* d_out, int out_size)
{
    const float* timef   = (const float*)d_in[0];
    const float* ppf     = (const float*)d_in[1];
    const float* pnf     = (const float*)d_in[2];
    const float* weightp = (const float*)d_in[3];
    const int*   signp   = (const int*)  d_in[4];
    const float* Wq  = (const float*)d_in[5];  const float* bq  = (const float*)d_in[6];
    const float* Wk  = (const float*)d_in[7];  const float* bk  = (const float*)d_in[8];
    const float* Wv  = (const float*)d_in[9];  const float* bv  = (const float*)d_in[10];
    const float* Wl  = (const float*)d_in[11]; const float* bl  = (const float*)d_in[12];
    const float* Wqp = (const float*)d_in[13]; const float* bqp = (const float*)d_in[14];
    const float* Wkp = (const float*)d_in[15]; const float* bkp = (const float*)d_in[16];
    const float* Wvp = (const float*)d_in[17]; const float* bvp = (const float*)d_in[18];
    float* out = (float*)d_out;

    const int smem2 = (8192 + 8192 + 8320 + 8192 + 1024 + 64) * (int)sizeof(float);

    cudaFuncSetAttribute(walk_attn_mma_kernel, cudaFuncAttributeMaxDynamicSharedMemorySize, SMEM_W_TOTAL);
    cudaFuncSetAttribute(path_attn_kernel, cudaFuncAttributeMaxDynamicSharedMemorySize, smem2);

    prep_w_kernel<<<48, 256>>>(Wq, Wk, Wv);
    walk_attn_mma_kernel<<<4096, 256, SMEM_W_TOTAL>>>(
        timef, ppf, pnf, weightp, signp, bq, bk, bv, Wl, bl);
    path_attn_kernel<<<256, 512, smem2>>>(
        Wqp, bqp, Wkp, bkp, Wvp, bvp, out);
}

// round 7
// speedup vs baseline: 2.3840x; 2.3840x over previous
#include <cuda_runtime.h>
#include <cuda_bf16.h>
#include <cstdint>

#define BATCH 128
#define NWALK 64
#define LWALK 32
#define TD 108
#define PD 19
#define FDIM 128
#define MDIM 128

// walk embeddings after Wl: [s][walk][128]
__device__ float g_emb[2 * BATCH * NWALK * MDIM];
// Wq/Wk hi-bf16 tiles in ldmatrix layout: [2][128 rows(j)][136 cols(f)]
__device__ __align__(16) __nv_bfloat16 g_wtile[2][17408];
// Wvl = Wv @ Wl (fp32), bvl = 32*bv@Wl + bl
__device__ float g_wvl[FDIM * MDIM];
__device__ float g_bvl[MDIM];

// ---------------- helpers ----------------------------------------------------
__device__ __forceinline__ uint32_t smem_to_u32(const void* p) {
    uint32_t a;
    asm("{ .reg .u64 t; cvta.to.shared.u64 t, %1; cvt.u32.u64 %0, t; }" : "=r"(a) : "l"(p));
    return a;
}
__device__ __forceinline__ void ldsm4(uint32_t r[4], uint32_t addr) {
    asm volatile("ldmatrix.sync.aligned.m8n8.x4.shared.b16 {%0,%1,%2,%3}, [%4];"
                 : "=r"(r[0]), "=r"(r[1]), "=r"(r[2]), "=r"(r[3]) : "r"(addr));
}
__device__ __forceinline__ void mma16816(float d[4], const uint32_t a[4], const uint32_t b[2]) {
    asm volatile("mma.sync.aligned.m16n8k16.row.col.f32.bf16.bf16.f32 "
                 "{%0,%1,%2,%3},{%4,%5,%6,%7},{%8,%9},{%0,%1,%2,%3};"
                 : "+f"(d[0]), "+f"(d[1]), "+f"(d[2]), "+f"(d[3])
                 : "r"(a[0]), "r"(a[1]), "r"(a[2]), "r"(a[3]), "r"(b[0]), "r"(b[1]));
}
__device__ __forceinline__ uint32_t pack_bf2(float a, float b) {
    __nv_bfloat162 h = __floats2bfloat162_rn(a, b);
    uint32_t r; memcpy(&r, &h, 4); return r;
}

// SMEM layout (bytes); tiles are 128 rows x 272B
#define XHI   0          // x_hi bf16 tile
#define WQ    34816      // Wq hi tile  -> k-tile after K GEMM
#define WK    69632      // Wk hi tile  -> x_lo tile after K GEMM
#define BQS   104448     // bq 128 f32
#define BKS   104960     // bk 128 f32
#define CPOFF 105472     // coefpart [8][32]
#define CSOFF 106496     // coef [4][32]
#define YS    107008     // y [4][128] f32
#define SMEM_W_TOTAL 109056
#define ROWB 272

// ---------------------------------------------------------------------------
// prep kernels
// ---------------------------------------------------------------------------
__global__ void prep_wtile_kernel(const float* __restrict__ Wq,
                                  const float* __restrict__ Wk)
{
    const int idx = blockIdx.x * 256 + threadIdx.x;  // 0..32767
    const int sel = idx >> 14;
    const int rem = idx & 16383;
    const int f   = rem >> 7;
    const int j   = rem & 127;
    const float* W = sel ? Wk : Wq;
    g_wtile[sel][j * 136 + f] = __float2bfloat16(W[f * FDIM + j]);
}

__global__ void prep_wvl_kernel(const float* __restrict__ Wv,
                                const float* __restrict__ Wl)
{
    const int idx = blockIdx.x * 256 + threadIdx.x;  // 0..16383
    const int f = idx >> 7;
    const int m = idx & 127;
    float acc = 0.f;
    #pragma unroll 8
    for (int k = 0; k < 128; k++)
        acc += Wv[f * FDIM + k] * Wl[k * MDIM + m];
    g_wvl[f * MDIM + m] = acc;
}

__global__ void prep_bvl_kernel(const float* __restrict__ bv,
                                const float* __restrict__ Wl,
                                const float* __restrict__ bl)
{
    const int m = threadIdx.x;
    float acc = bl[m];
    #pragma unroll 8
    for (int k = 0; k < 128; k++)
        acc += 32.f * bv[k] * Wl[k * MDIM + m];
    g_bvl[m] = acc;
}

// ---------------------------------------------------------------------------
// Walk kernel: 1 CTA = 4 walks of one sign. grid = 4096, 256 threads, 2/SM.
// ---------------------------------------------------------------------------
__global__ __launch_bounds__(256, 2)
void walk_attn_mma_kernel(
    const float* __restrict__ timef,
    const float* __restrict__ ppf,
    const float* __restrict__ pnf,
    const float* __restrict__ weightp,
    const int*   __restrict__ signp,
    const float* __restrict__ bq, const float* __restrict__ bk)
{
    extern __shared__ char smem[];
    const uint32_t sb = smem_to_u32(smem);
    const int tid = threadIdx.x;
    const int w   = tid >> 5;
    const int l   = tid & 31;
    const int m0  = w * 16;
    const int walk_l = w >> 1;
    const int bx  = blockIdx.x;
    const int s   = bx >> 11;
    const int g   = bx & 2047;

    float* bq_s   = (float*)(smem + BQS);
    float* bk_s   = (float*)(smem + BKS);
    float* cp_s   = (float*)(smem + CPOFF);
    float* coef_s = (float*)(smem + CSOFF);
    float* y_s    = (float*)(smem + YS);

    if (tid < 128) { bq_s[tid] = bq[tid]; bk_s[tid] = bk[tid]; }

    // ---- copy Wq/Wk hi tiles (69632B contiguous) ----
    {
        const uint4* src = (const uint4*)g_wtile;
        uint4* dst = (uint4*)(smem + WQ);
        #pragma unroll
        for (int i = 0; i < 17; i++) dst[tid + 256 * i] = src[tid + 256 * i];
    }

    // ---- build X hi tile; stash x_lo in registers ----
    uint32_t xlo[32];
    #pragma unroll 4
    for (int it = 0; it < 32; it++) {
        const int id = tid + 256 * it;
        const int r  = id >> 6;
        const int f0 = (id & 63) * 2;
        const int wg = g * 4 + (r >> 5);
        const int e  = wg * LWALK + (r & 31);
        float x0, x1;
        {
            const int f = f0;
            if (f < PD) {
                const bool usep = (signp[e] > 0) != (s == 1);
                x0 = usep ? ppf[e * PD + f] : pnf[e * PD + f];
            } else x0 = timef[e * TD + (f - PD)];
        }
        {
            const int f = f0 + 1;
            if (f < PD) {
                const bool usep = (signp[e] > 0) != (s == 1);
                x1 = usep ? ppf[e * PD + f] : pnf[e * PD + f];
            } else if (f < FDIM - 1) x1 = timef[e * TD + (f - PD)];
            else x1 = weightp[e];
        }
        const float h0 = __bfloat162float(__float2bfloat16(x0));
        const float h1 = __bfloat162float(__float2bfloat16(x1));
        *(uint32_t*)(smem + XHI + (uint32_t)r * ROWB + (uint32_t)f0 * 2) = pack_bf2(h0, h1);
        xlo[it] = pack_bf2(x0 - h0, x1 - h1);
    }
    __syncthreads();

    // fragment address components
    const uint32_t aRow = (uint32_t)(m0 + (l & 15));
    const uint32_t aCol = (uint32_t)((l >> 4) << 4);
    const uint32_t aHiB = sb + XHI + aRow * ROWB + aCol;
    const uint32_t bRow = (uint32_t)((l & 7) + ((l >> 4) << 3));
    const uint32_t bCol = (uint32_t)(((l >> 3) & 1) << 4);
    const int r1 = m0 + (l >> 2);
    const int c0 = (l & 3) * 2;

    // ================= Q GEMM (single-term, halves to limit regs) ==========
    uint32_t qph[16][2];
    #pragma unroll
    for (int half = 0; half < 2; half++) {
        float acc[8][4];
        #pragma unroll
        for (int n = 0; n < 8; n++)
            #pragma unroll
            for (int i = 0; i < 4; i++) acc[n][i] = 0.f;
        #pragma unroll
        for (int ks = 0; ks < 8; ks++) {
            uint32_t ah[4];
            ldsm4(ah, aHiB + ks * 32);
            #pragma unroll
            for (int np = 0; np < 4; np++) {
                uint32_t bh[4];
                ldsm4(bh, sb + WQ + (half * 64 + np * 16 + bRow) * ROWB + bCol + ks * 32);
                mma16816(acc[2*np],   ah, bh);
                mma16816(acc[2*np+1], ah, bh + 2);
            }
        }
        #pragma unroll
        for (int ln = 0; ln < 8; ln++) {
            const int nt = half * 8 + ln;
            const int cc = nt * 8 + c0;
            qph[nt][0] = pack_bf2(acc[ln][0] + bq_s[cc], acc[ln][1] + bq_s[cc + 1]);
            qph[nt][1] = pack_bf2(acc[ln][2] + bq_s[cc], acc[ln][3] + bq_s[cc + 1]);
        }
    }
    __syncthreads();   // all Wq reads done -> WQ region reusable (k-tile)

    // ================= K GEMM (single-term), k -> WQ region ================
    #pragma unroll
    for (int half = 0; half < 2; half++) {
        float acc[8][4];
        #pragma unroll
        for (int n = 0; n < 8; n++)
            #pragma unroll
            for (int i = 0; i < 4; i++) acc[n][i] = 0.f;
        #pragma unroll
        for (int ks = 0; ks < 8; ks++) {
            uint32_t ah[4];
            ldsm4(ah, aHiB + ks * 32);
            #pragma unroll
            for (int np = 0; np < 4; np++) {
                uint32_t bh[4];
                ldsm4(bh, sb + WK + (half * 64 + np * 16 + bRow) * ROWB + bCol + ks * 32);
                mma16816(acc[2*np],   ah, bh);
                mma16816(acc[2*np+1], ah, bh + 2);
            }
        }
        #pragma unroll
        for (int ln = 0; ln < 8; ln++) {
            const int nt = half * 8 + ln;
            const int cc = nt * 8 + c0;
            *(uint32_t*)(smem + WQ + (uint32_t)r1 * ROWB + (uint32_t)cc * 2) =
                pack_bf2(acc[ln][0] + bk_s[cc], acc[ln][1] + bk_s[cc + 1]);
            *(uint32_t*)(smem + WQ + (uint32_t)(r1 + 8) * ROWB + (uint32_t)cc * 2) =
                pack_bf2(acc[ln][2] + bk_s[cc], acc[ln][3] + bk_s[cc + 1]);
        }
    }
    __syncthreads();   // k visible; Wk reads done -> WK region reusable (x_lo)

    // ---- dump x_lo regs into WK region ----
    #pragma unroll 4
    for (int it = 0; it < 32; it++) {
        const int id = tid + 256 * it;
        const int r  = id >> 6;
        const int f0 = (id & 63) * 2;
        *(uint32_t*)(smem + WK + (uint32_t)r * ROWB + (uint32_t)f0 * 2) = xlo[it];
    }

    // ================= scores (single-term) =================
    float sacc[4][4];
    #pragma unroll
    for (int n = 0; n < 4; n++)
        #pragma unroll
        for (int i = 0; i < 4; i++) sacc[n][i] = 0.f;
    {
        const uint32_t kRow = (uint32_t)(walk_l * 32) + bRow;
        #pragma unroll
        for (int ks = 0; ks < 8; ks++) {
            const uint32_t ah[4] = {qph[2*ks][0], qph[2*ks][1], qph[2*ks+1][0], qph[2*ks+1][1]};
            #pragma unroll
            for (int np = 0; np < 2; np++) {
                uint32_t bh[4];
                ldsm4(bh, sb + WQ + (kRow + np * 16) * ROWB + bCol + ks * 32);
                mma16816(sacc[2*np],   ah, bh);
                mma16816(sacc[2*np+1], ah, bh + 2);
            }
        }
    }

    // ---- softmax rows + 16-row column sums ----
    {
        const float scale = 0.08838834764831845f;
        float t[4][2];
        #pragma unroll
        for (int h = 0; h < 2; h++) {
            float x[4][2], mx = -1e30f;
            #pragma unroll
            for (int nt = 0; nt < 4; nt++) {
                x[nt][0] = sacc[nt][2*h]     * scale;
                x[nt][1] = sacc[nt][2*h + 1] * scale;
                mx = fmaxf(mx, fmaxf(x[nt][0], x[nt][1]));
            }
            mx = fmaxf(mx, __shfl_xor_sync(0xffffffffu, mx, 1));
            mx = fmaxf(mx, __shfl_xor_sync(0xffffffffu, mx, 2));
            float sum = 0.f;
            #pragma unroll
            for (int nt = 0; nt < 4; nt++) {
                x[nt][0] = __expf(x[nt][0] - mx);
                x[nt][1] = __expf(x[nt][1] - mx);
                sum += x[nt][0] + x[nt][1];
            }
            sum += __shfl_xor_sync(0xffffffffu, sum, 1);
            sum += __shfl_xor_sync(0xffffffffu, sum, 2);
            const float inv = 1.f / sum;
            #pragma unroll
            for (int nt = 0; nt < 4; nt++) {
                const float p0 = x[nt][0] * inv;
                const float p1 = x[nt][1] * inv;
                if (h == 0) { t[nt][0] = p0;  t[nt][1] = p1; }
                else        { t[nt][0] += p0; t[nt][1] += p1; }
            }
        }
        #pragma unroll
        for (int o = 4; o <= 16; o <<= 1)
            #pragma unroll
            for (int nt = 0; nt < 4; nt++) {
                t[nt][0] += __shfl_xor_sync(0xffffffffu, t[nt][0], o);
                t[nt][1] += __shfl_xor_sync(0xffffffffu, t[nt][1], o);
            }
        if (l < 4) {
            #pragma unroll
            for (int nt = 0; nt < 4; nt++) {
                cp_s[w * 32 + nt * 8 + l * 2]     = t[nt][0];
                cp_s[w * 32 + nt * 8 + l * 2 + 1] = t[nt][1];
            }
        }
    }
    __syncthreads();

    if (tid < 128) {
        const int wk = tid >> 5, m = tid & 31;
        coef_s[tid] = cp_s[(2 * wk) * 32 + m] + cp_s[(2 * wk + 1) * 32 + m];
    }
    __syncthreads();   // coef visible; x_lo stores also ordered by barriers above

    // ---- y[walk][f] = sum_m coef[walk][m] * x[m][f]  (x = hi + lo) ----
    {
        const int wk = tid >> 6;          // 0..3
        const int fp = tid & 63;          // f-pair
        float y0 = 0.f, y1 = 0.f;
        const uint32_t rowbase = (uint32_t)(wk * 32) * ROWB + (uint32_t)fp * 4;
        #pragma unroll 8
        for (int m = 0; m < 32; m++) {
            const float c = coef_s[wk * 32 + m];
            const uint32_t hp = *(const uint32_t*)(smem + XHI + rowbase + (uint32_t)m * ROWB);
            const uint32_t lp = *(const uint32_t*)(smem + WK  + rowbase + (uint32_t)m * ROWB);
            __nv_bfloat162 h2, l2;
            memcpy(&h2, &hp, 4); memcpy(&l2, &lp, 4);
            y0 += c * (__bfloat162float(h2.x) + __bfloat162float(l2.x));
            y1 += c * (__bfloat162float(h2.y) + __bfloat162float(l2.y));
        }
        y_s[wk * 128 + fp * 2]     = y0;
        y_s[wk * 128 + fp * 2 + 1] = y1;
    }
    __syncthreads();

    // ---- emb = y @ Wvl + bvl  (fp32) ----
    #pragma unroll
    for (int rep = 0; rep < 2; rep++) {
        const int idx = tid + rep * 256;
        const int wk = idx >> 7;
        const int m  = idx & 127;
        float acc = g_bvl[m];
        #pragma unroll 8
        for (int f = 0; f < 128; f++)
            acc += y_s[wk * 128 + f] * g_wvl[f * MDIM + m];
        const int wg = g * 4 + wk;
        g_emb[((size_t)(s * 8192 + wg)) * MDIM + m] = acc;
    }
}

// ---------------------------------------------------------------------------
// Path kernel (fp32): per-(b, sign) attention over L=64, D=128.
// ---------------------------------------------------------------------------
__global__ void path_attn_kernel(
    const float* __restrict__ Wqp, const float* __restrict__ bqp,
    const float* __restrict__ Wkp, const float* __restrict__ bkp,
    const float* __restrict__ Wvp, const float* __restrict__ bvp,
    float* __restrict__ out)
{
    extern __shared__ float sm[];
    float* xT       = sm;
    float* q        = xT + 8192;
    float* kk       = q + 8192;
    float* v        = kk + 8320;
    float* coefpart = v + 8192;
    float* coef     = coefpart + 1024;

    const int bx  = blockIdx.x;
    const int s   = bx >> 7;
    const int b   = bx & 127;
    const int tid = threadIdx.x;

    const float* x = g_emb + ((size_t)(s * BATCH + b) * NWALK) * MDIM;
    for (int id = tid; id < 64 * 128; id += 512) {
        const int l = id & 63;
        const int d = id >> 6;
        xT[d * 64 + l] = x[l * 128 + d];
    }
    __syncthreads();
    {
        const int j  = tid & 127;
        const int rg = tid >> 7;
        float accq[16], acck[16], accv[16];
        const float bqj = bqp[j], bkj = bkp[j], bvj = bvp[j];
        #pragma unroll
        for (int i = 0; i < 16; i++) { accq[i] = bqj; acck[i] = bkj; accv[i] = bvj; }
        const float4* xT4 = (const float4*)xT;
        #pragma unroll 2
        for (int f = 0; f < FDIM; f++) {
            const float wq = Wqp[f * FDIM + j];
            const float wk = Wkp[f * FDIM + j];
            const float wv = Wvp[f * FDIM + j];
            #pragma unroll
            for (int k4 = 0; k4 < 4; k4++) {
                const float4 xv = xT4[f * 16 + rg * 4 + k4];
                accq[k4*4+0] += xv.x * wq; accq[k4*4+1] += xv.y * wq;
                accq[k4*4+2] += xv.z * wq; accq[k4*4+3] += xv.w * wq;
                acck[k4*4+0] += xv.x * wk; acck[k4*4+1] += xv.y * wk;
                acck[k4*4+2] += xv.z * wk; acck[k4*4+3] += xv.w * wk;
                accv[k4*4+0] += xv.x * wv; accv[k4*4+1] += xv.y * wv;
                accv[k4*4+2] += xv.z * wv; accv[k4*4+3] += xv.w * wv;
            }
        }
        #pragma unroll
        for (int i = 0; i < 16; i++) {
            const int r = rg * 16 + i;
            q[r * 128 + j] = accq[i];
            kk[r * 130 + j] = acck[i];
            v[r * 128 + j] = accv[i];
        }
    }
    __syncthreads();
    {
        const int m = tid & 31;
        const int w = tid >> 5;
        float sc0[4] = {0.f,0.f,0.f,0.f};
        float sc1[4] = {0.f,0.f,0.f,0.f};
        for (int f = 0; f < FDIM; f++) {
            const float kf0 = kk[m * 130 + f];
            const float kf1 = kk[(m + 32) * 130 + f];
            #pragma unroll
            for (int i = 0; i < 4; i++) {
                const float qf = q[(4 * w + i) * 128 + f];
                sc0[i] += qf * kf0;
                sc1[i] += qf * kf1;
            }
        }
        const float scale = 0.08838834764831845f;
        float cp0 = 0.f, cp1 = 0.f;
        #pragma unroll
        for (int i = 0; i < 4; i++) {
            float x0 = sc0[i] * scale;
            float x1 = sc1[i] * scale;
            float mx = fmaxf(x0, x1);
            #pragma unroll
            for (int o = 16; o > 0; o >>= 1)
                mx = fmaxf(mx, __shfl_xor_sync(0xffffffffu, mx, o));
            const float e0 = __expf(x0 - mx);
            const float e1 = __expf(x1 - mx);
            float sme = e0 + e1;
            #pragma unroll
            for (int o = 16; o > 0; o >>= 1)
                sme += __shfl_xor_sync(0xffffffffu, sme, o);
            const float inv = 1.f / sme;
            cp0 += e0 * inv;
            cp1 += e1 * inv;
        }
        coefpart[w * 64 + m]      = cp0;
        coefpart[w * 64 + m + 32] = cp1;
    }
    __syncthreads();
    if (tid < 64) {
        float c = 0.f;
        #pragma unroll
        for (int w = 0; w < 16; w++) c += coefpart[w * 64 + tid];
        coef[tid] = c;
    }
    __syncthreads();
    if (tid < 128) {
        float o = 0.f;
        #pragma unroll 8
        for (int m = 0; m < 64; m++) o += coef[m] * v[m * 128 + tid];
        out[(size_t)(s * BATCH + b) * MDIM + tid] = o;
    }
}

// ---------------------------------------------------------------------------
extern "C" void kernel_launch(void* const* d_in, const int* in_sizes, int n_in,
                              void* d_out, int out_size)
{
    const float* timef   = (const float*)d_in[0];
    const float* ppf     = (const float*)d_in[1];
    const float* pnf     = (const float*)d_in[2];
    const float* weightp = (const float*)d_in[3];
    const int*   signp   = (const int*)  d_in[4];
    const float* Wq  = (const float*)d_in[5];  const float* bq  = (const float*)d_in[6];
    const float* Wk  = (const float*)d_in[7];  const float* bk  = (const float*)d_in[8];
    const float* Wv  = (const float*)d_in[9];
    const float* Wl  = (const float*)d_in[11]; const float* bl  = (const float*)d_in[12];
    const float* bv  = (const float*)d_in[10];
    const float* Wqp = (const float*)d_in[13]; const float* bqp = (const float*)d_in[14];
    const float* Wkp = (const float*)d_in[15]; const float* bkp = (const float*)d_in[16];
    const float* Wvp = (const float*)d_in[17]; const float* bvp = (const float*)d_in[18];
    float* out = (float*)d_out;

    const int smem2 = (8192 + 8192 + 8320 + 8192 + 1024 + 64) * (int)sizeof(float);

    cudaFuncSetAttribute(walk_attn_mma_kernel, cudaFuncAttributeMaxDynamicSharedMemorySize, SMEM_W_TOTAL);
    cudaFuncSetAttribute(path_attn_kernel, cudaFuncAttributeMaxDynamicSharedMemorySize, smem2);

    prep_wtile_kernel<<<128, 256>>>(Wq, Wk);
    prep_wvl_kernel<<<64, 256>>>(Wv, Wl);
    prep_bvl_kernel<<<1, 128>>>(bv, Wl, bl);
    walk_attn_mma_kernel<<<4096, 256, SMEM_W_TOTAL>>>(
        timef, ppf, pnf, weightp, signp, bq, bk);
    path_attn_kernel<<<256, 512, smem2>>>(
        Wqp, bqp, Wkp, bkp, Wvp, bvp, out);
}